// round 3
// baseline (speedup 1.0000x reference)
#include <cuda_runtime.h>
#include <cuda_bf16.h>

#define W 512
#define H 512
#define TH 16      // output rows per block (must be even)
#define EPS 1e-4f

__device__ __forceinline__ float sqrt_approx(float x) {
    float y;
    asm("sqrt.approx.f32 %0, %1;" : "=f"(y) : "f"(x));
    return y;
}

// Fetch one input row segment and pre-reduce to:
//   d[j] = s[j] - s[j+2]            (horizontal part of gx)
//   t[j] = s[j] + 2*s[j+1] + s[j+2] (horizontal part of gy)
// Halo values come from neighbor lanes via shuffle; only warp-edge lanes
// (0 and 31) do a real (1-wavefront, predicated) load.
__device__ __forceinline__ void fetch_row(const float* __restrict__ img,
                                          int y, int x0, int lane,
                                          float d[4], float t[4]) {
    float4 v;
    float l, r;
    if ((unsigned)y < (unsigned)H) {
        const float* row = img + (size_t)y * W;
        v = *(const float4*)(row + x0);
        l = __shfl_up_sync(0xffffffffu, v.w, 1);
        r = __shfl_down_sync(0xffffffffu, v.x, 1);
        if (lane == 0)  l = (x0 > 0)     ? __ldg(row + x0 - 1) : 0.f;
        if (lane == 31) r = (x0 + 4 < W) ? __ldg(row + x0 + 4) : 0.f;
    } else {
        v = make_float4(0.f, 0.f, 0.f, 0.f);
        l = 0.f;
        r = 0.f;
    }

    float s0 = l, s1 = v.x, s2 = v.y, s3 = v.z, s4 = v.w, s5 = r;
    d[0] = s0 - s2;
    d[1] = s1 - s3;
    d[2] = s2 - s4;
    d[3] = s3 - s5;
    t[0] = fmaf(2.f, s1, s0 + s2);
    t[1] = fmaf(2.f, s2, s1 + s3);
    t[2] = fmaf(2.f, s3, s2 + s4);
    t[3] = fmaf(2.f, s4, s3 + s5);
}

// gx = (dA + 2 dB + dC)/4, gy = (tA - tC)/4  ->  0.25*sqrt(u^2+v^2+16*eps)
__device__ __forceinline__ float4 magnitude(const float dA[4], const float tA[4],
                                            const float dB[4],
                                            const float dC[4], const float tC[4]) {
    float4 res;
    float u, v;

    u = dA[0] + 2.f * dB[0] + dC[0];
    v = tA[0] - tC[0];
    res.x = 0.25f * sqrt_approx(fmaf(u, u, fmaf(v, v, 16.f * EPS)));

    u = dA[1] + 2.f * dB[1] + dC[1];
    v = tA[1] - tC[1];
    res.y = 0.25f * sqrt_approx(fmaf(u, u, fmaf(v, v, 16.f * EPS)));

    u = dA[2] + 2.f * dB[2] + dC[2];
    v = tA[2] - tC[2];
    res.z = 0.25f * sqrt_approx(fmaf(u, u, fmaf(v, v, 16.f * EPS)));

    u = dA[3] + 2.f * dB[3] + dC[3];
    v = tA[3] - tC[3];
    res.w = 0.25f * sqrt_approx(fmaf(u, u, fmaf(v, v, 16.f * EPS)));
    return res;
}

__global__ __launch_bounds__(128) void sobel_kernel(const float* __restrict__ in,
                                                    float* __restrict__ out) {
    const int b    = blockIdx.z;
    const int lane = threadIdx.x & 31;
    const int x0   = threadIdx.x * 4;        // 128 threads * 4 cols = 512 = W
    const int y0   = blockIdx.y * TH;

    const float* img = in  + (size_t)b * H * W;
    float*       o   = out + (size_t)b * H * W;

    // Pre-reduced rolling window rows
    float dA[4], tA[4], dB[4], tB[4], dC[4], tC[4], dD[4], tD[4];

    fetch_row(img, y0 - 1, x0, lane, dA, tA);
    fetch_row(img, y0,     x0, lane, dB, tB);

#pragma unroll
    for (int i = 0; i < TH / 2; i++) {
        const int y = y0 + 2 * i;

        // Issue both new row fetches up front (independent loads in flight)
        fetch_row(img, y + 1, x0, lane, dC, tC);
        fetch_row(img, y + 2, x0, lane, dD, tD);

        // output row y   : window A(y-1), B(y), C(y+1)
        float4 r0 = magnitude(dA, tA, dB, dC, tC);
        // output row y+1 : window B(y),   C(y+1), D(y+2)
        float4 r1 = magnitude(dB, tB, dC, dD, tD);

        *(float4*)(o + (size_t)y       * W + x0) = r0;
        *(float4*)(o + (size_t)(y + 1) * W + x0) = r1;

        // slide window down by 2 (full unroll -> register renaming, no moves)
#pragma unroll
        for (int j = 0; j < 4; j++) {
            dA[j] = dC[j]; tA[j] = tC[j];
            dB[j] = dD[j]; tB[j] = tD[j];
        }
    }
}

extern "C" void kernel_launch(void* const* d_in, const int* in_sizes, int n_in,
                              void* d_out, int out_size) {
    const float* x = (const float*)d_in[0];
    float* out = (float*)d_out;

    const int total = in_sizes[0];          // B * 1 * H * W
    const int B = total / (H * W);

    dim3 block(128, 1, 1);
    dim3 grid(1, H / TH, B);
    sobel_kernel<<<grid, block>>>(x, out);
}

// round 6
// speedup vs baseline: 1.6342x; 1.6342x over previous
#include <cuda_runtime.h>
#include <cuda_bf16.h>

#define W 512
#define H 512
#define TH 16      // output rows per block (must be even)
#define EPS 1e-4f

__device__ __forceinline__ float sqrt_approx(float x) {
    float y;
    asm("sqrt.approx.f32 %0, %1;" : "=f"(y) : "f"(x));
    return y;
}

// Issue raw loads for one input row segment (float4 body + 2 halo scalars).
__device__ __forceinline__ void fetch_raw(const float* __restrict__ img,
                                          int y, int x0,
                                          float4& v, float& l, float& r) {
    if ((unsigned)y < (unsigned)H) {
        const float* row = img + (size_t)y * W;
        v = *(const float4*)(row + x0);
        l = (x0 > 0)     ? __ldg(row + x0 - 1) : 0.f;
        r = (x0 + 4 < W) ? __ldg(row + x0 + 4) : 0.f;
    } else {
        v = make_float4(0.f, 0.f, 0.f, 0.f);
        l = 0.f; r = 0.f;
    }
}

// Pre-reduce raw row into horizontal-diff d[] (gx part) and smooth t[] (gy part).
__device__ __forceinline__ void reduce_row(const float4& v, float l, float r,
                                           float d[4], float t[4]) {
    float s0 = l, s1 = v.x, s2 = v.y, s3 = v.z, s4 = v.w, s5 = r;
    d[0] = s0 - s2;
    d[1] = s1 - s3;
    d[2] = s2 - s4;
    d[3] = s3 - s5;
    t[0] = fmaf(2.f, s1, s0 + s2);
    t[1] = fmaf(2.f, s2, s1 + s3);
    t[2] = fmaf(2.f, s3, s2 + s4);
    t[3] = fmaf(2.f, s4, s3 + s5);
}

// gx = (dA + 2 dB + dC)/4, gy = (tA - tC)/4  ->  0.25*sqrt(u^2+v^2+16*eps)
__device__ __forceinline__ float4 magnitude(const float dA[4], const float tA[4],
                                            const float dB[4],
                                            const float dC[4], const float tC[4]) {
    float4 res;
    float u, v;

    u = dA[0] + 2.f * dB[0] + dC[0];
    v = tA[0] - tC[0];
    res.x = 0.25f * sqrt_approx(fmaf(u, u, fmaf(v, v, 16.f * EPS)));

    u = dA[1] + 2.f * dB[1] + dC[1];
    v = tA[1] - tC[1];
    res.y = 0.25f * sqrt_approx(fmaf(u, u, fmaf(v, v, 16.f * EPS)));

    u = dA[2] + 2.f * dB[2] + dC[2];
    v = tA[2] - tC[2];
    res.z = 0.25f * sqrt_approx(fmaf(u, u, fmaf(v, v, 16.f * EPS)));

    u = dA[3] + 2.f * dB[3] + dC[3];
    v = tA[3] - tC[3];
    res.w = 0.25f * sqrt_approx(fmaf(u, u, fmaf(v, v, 16.f * EPS)));
    return res;
}

__global__ __launch_bounds__(128, 8) void sobel_kernel(const float* __restrict__ in,
                                                       float* __restrict__ out) {
    const int b  = blockIdx.z;
    const int x0 = threadIdx.x * 4;          // 128 threads * 4 cols = 512 = W
    const int y0 = blockIdx.y * TH;

    const float* img = in  + (size_t)b * H * W;
    float*       o   = out + (size_t)b * H * W;

    // Reduced rolling-window rows
    float dA[4], tA[4], dB[4], tB[4], dC[4], tC[4], dD[4], tD[4];

    // Prefetched raw rows for the NEXT iteration (software pipeline, depth 1)
    float4 p0v, p1v;
    float  p0l, p0r, p1l, p1r;

    {
        float4 vA, vB; float lA, rA, lB, rB;
        fetch_raw(img, y0 - 1, x0, vA, lA, rA);   // 12 independent LDGs
        fetch_raw(img, y0,     x0, vB, lB, rB);   // batched up front
        fetch_raw(img, y0 + 1, x0, p0v, p0l, p0r);
        fetch_raw(img, y0 + 2, x0, p1v, p1l, p1r);
        reduce_row(vA, lA, rA, dA, tA);
        reduce_row(vB, lB, rB, dB, tB);
    }

#pragma unroll
    for (int i = 0; i < TH / 2; i++) {
        const int y = y0 + 2 * i;

        // 1) Issue next iteration's loads FIRST (overlap with this iter's compute)
        float4 n0v, n1v;
        float  n0l, n0r, n1l, n1r;
        if (i < TH / 2 - 1) {                 // compile-time under full unroll
            fetch_raw(img, y + 3, x0, n0v, n0l, n0r);
            fetch_raw(img, y + 4, x0, n1v, n1l, n1r);
        }

        // 2) Consume loads issued one iteration ago
        reduce_row(p0v, p0l, p0r, dC, tC);    // row y+1
        reduce_row(p1v, p1l, p1r, dD, tD);    // row y+2

        // output row y   : window A(y-1), B(y), C(y+1)
        float4 r0 = magnitude(dA, tA, dB, dC, tC);
        // output row y+1 : window B(y),   C(y+1), D(y+2)
        float4 r1 = magnitude(dB, tB, dC, dD, tD);

        __stcs((float4*)(o + (size_t)y       * W + x0), r0);
        __stcs((float4*)(o + (size_t)(y + 1) * W + x0), r1);

        // 3) Rotate window + pipeline registers (full unroll -> renaming)
#pragma unroll
        for (int j = 0; j < 4; j++) {
            dA[j] = dC[j]; tA[j] = tC[j];
            dB[j] = dD[j]; tB[j] = tD[j];
        }
        if (i < TH / 2 - 1) {
            p0v = n0v; p0l = n0l; p0r = n0r;
            p1v = n1v; p1l = n1l; p1r = n1r;
        }
    }
}

extern "C" void kernel_launch(void* const* d_in, const int* in_sizes, int n_in,
                              void* d_out, int out_size) {
    const float* x = (const float*)d_in[0];
    float* out = (float*)d_out;

    const int total = in_sizes[0];          // B * 1 * H * W
    const int B = total / (H * W);

    dim3 block(128, 1, 1);
    dim3 grid(1, H / TH, B);
    sobel_kernel<<<grid, block>>>(x, out);
}